// round 1
// baseline (speedup 1.0000x reference)
#include <cuda_runtime.h>
#include <math.h>

// ---------------- problem constants ----------------
#define NLAYERS 8
#define Dh      768
#define Eh      1536
#define Nst     16
#define KC      4
#define DTRW    48
#define Bb      2
#define Ll      2048
#define ROWS    (Bb*Ll)          // 4096
#define SSMW    (DTRW + 2*Nst)   // 80
#define EPSV    1e-5f

// ---------------- scratch (static device, no allocs) ----------------
__device__ float g_h   [ROWS*Dh];
__device__ float g_hn  [ROWS*Dh];
__device__ float g_proj[ROWS*2*Eh];
__device__ float g_u   [ROWS*Eh];
__device__ float g_ssm [ROWS*SSMW];
__device__ float g_dt  [ROWS*Eh];
__device__ float g_y   [ROWS*Eh];

// ---------------- small kernels ----------------
__global__ void copy_kernel(const float* __restrict__ src, float* __restrict__ dst, int n) {
    int i = blockIdx.x * 256 + threadIdx.x;
    if (i < n) dst[i] = src[i];
}

// One block per row (D=768), 256 threads
__global__ void __launch_bounds__(256) rmsnorm_kernel(
    const float* __restrict__ x, const float* __restrict__ w, float* __restrict__ out)
{
    __shared__ float sh[8];
    int row = blockIdx.x;
    const float* xr = x + (size_t)row * Dh;
    float s = 0.f;
    #pragma unroll
    for (int i = threadIdx.x; i < Dh; i += 256) { float v = xr[i]; s += v * v; }
    // warp reduce
    #pragma unroll
    for (int o = 16; o; o >>= 1) s += __shfl_xor_sync(0xffffffffu, s, o);
    int wid = threadIdx.x >> 5, lane = threadIdx.x & 31;
    if (lane == 0) sh[wid] = s;
    __syncthreads();
    if (wid == 0) {
        float v = (lane < 8) ? sh[lane] : 0.f;
        #pragma unroll
        for (int o = 4; o; o >>= 1) v += __shfl_xor_sync(0xffffffffu, v, o);
        if (lane == 0) sh[0] = rsqrtf(v * (1.f / Dh) + EPSV);
    }
    __syncthreads();
    float rs = sh[0];
    #pragma unroll
    for (int i = threadIdx.x; i < Dh; i += 256)
        out[(size_t)row * Dh + i] = xr[i] * rs * w[i];
}

// ---------------- generic fp32 GEMM: C[m,n] = sum_k A[m,k]*B[n,k] ----------------
// A: (M,K) row-major with leading dim lda; B: (N,K) row-major ldb=K; C: (M,N) ldc=N
// mode 0: store; mode 1: C = extra[m,n] + acc (residual); mode 2: C = softplus(acc + extra[n])
#define BM 128
#define BN 64
#define BKK 16
#define TM 8
#define TN 4

__global__ void __launch_bounds__(256) gemm_nt(
    const float* __restrict__ A, int lda,
    const float* __restrict__ Bw,
    const float* __restrict__ extra,
    float* __restrict__ C,
    int M, int N, int Kd, int mode)
{
    __shared__ float As[BKK][BM];
    __shared__ float Bs[BKK][BN];

    int bm = blockIdx.y * BM;
    int bn = blockIdx.x * BN;
    int t  = threadIdx.x;
    int tx = t & 15, ty = t >> 4;

    float acc[TM][TN];
    #pragma unroll
    for (int i = 0; i < TM; i++)
        #pragma unroll
        for (int j = 0; j < TN; j++) acc[i][j] = 0.f;

    int lrow = t >> 2;           // 0..63
    int lcol = (t & 3) << 2;     // 0,4,8,12

    const float* Aptr = A + (size_t)bm * lda;

    for (int k0 = 0; k0 < Kd; k0 += BKK) {
        // A tile: 128 rows x 16 cols, two passes of 64 rows, float4 along K
        #pragma unroll
        for (int p = 0; p < 2; ++p) {
            int r = lrow + p * 64;
            float4 v = *(const float4*)(Aptr + (size_t)r * lda + k0 + lcol);
            As[lcol + 0][r] = v.x; As[lcol + 1][r] = v.y;
            As[lcol + 2][r] = v.z; As[lcol + 3][r] = v.w;
        }
        // B tile: 64 rows x 16 cols
        {
            int r = lrow;
            int n = bn + r;
            float4 v = make_float4(0.f, 0.f, 0.f, 0.f);
            if (n < N) v = *(const float4*)(Bw + (size_t)n * Kd + k0 + lcol);
            Bs[lcol + 0][r] = v.x; Bs[lcol + 1][r] = v.y;
            Bs[lcol + 2][r] = v.z; Bs[lcol + 3][r] = v.w;
        }
        __syncthreads();

        #pragma unroll
        for (int k = 0; k < BKK; ++k) {
            float4 a0 = *(const float4*)(&As[k][ty * TM]);
            float4 a1 = *(const float4*)(&As[k][ty * TM + 4]);
            float4 b0 = *(const float4*)(&Bs[k][tx * TN]);
            float av[TM] = {a0.x, a0.y, a0.z, a0.w, a1.x, a1.y, a1.z, a1.w};
            float bv[TN] = {b0.x, b0.y, b0.z, b0.w};
            #pragma unroll
            for (int i = 0; i < TM; i++)
                #pragma unroll
                for (int j = 0; j < TN; j++)
                    acc[i][j] += av[i] * bv[j];
        }
        __syncthreads();
    }

    #pragma unroll
    for (int i = 0; i < TM; i++) {
        int m = bm + ty * TM + i;
        #pragma unroll
        for (int j = 0; j < TN; j++) {
            int n = bn + tx * TN + j;
            if (n < N) {
                float v = acc[i][j];
                if (mode == 1) v += extra[(size_t)m * N + n];
                else if (mode == 2) {
                    v += extra[n];
                    v = (v > 20.f) ? v : log1pf(expf(v));   // softplus
                }
                C[(size_t)m * N + n] = v;
            }
        }
    }
}

// ---------------- causal depthwise conv (K=4) + bias + silu ----------------
__global__ void conv_silu_kernel(
    const float* __restrict__ proj,   // (ROWS, 2E), u part = cols [0,E)
    const float* __restrict__ cw,     // (E, K)
    const float* __restrict__ cb,     // (E)
    float* __restrict__ out)          // (ROWS, E)
{
    int idx = blockIdx.x * 256 + threadIdx.x;
    if (idx >= ROWS * Eh) return;
    int e  = idx % Eh;
    int bl = idx / Eh;
    int l  = bl % Ll;
    float acc = cb[e];
    #pragma unroll
    for (int k = 0; k < KC; ++k) {
        int ls = l - (KC - 1) + k;
        if (ls >= 0)
            acc += cw[e * KC + k] * proj[(size_t)(bl + ls - l) * (2 * Eh) + e];
    }
    out[(size_t)bl * Eh + e] = acc / (1.f + __expf(-acc));   // silu
}

// ---------------- selective scan ----------------
// thread = (e, n); 16-lane segments reduce over n; lane 0 writes gated output.
__global__ void __launch_bounds__(256) scan_kernel(
    const float* __restrict__ dtb,    // (ROWS, E)
    const float* __restrict__ ub,     // (ROWS, E)
    const float* __restrict__ ssm,    // (ROWS, 80): [0:48)=dt_r, [48:64)=B, [64:80)=C
    const float* __restrict__ proj,   // (ROWS, 2E): gate = cols [E,2E)
    const float* __restrict__ A_log,  // (E, N) for this layer
    const float* __restrict__ Dskip,  // (E)
    float* __restrict__ yb)           // (ROWS, E)
{
    int blk = blockIdx.x;             // 0 .. Bb*E/16 - 1
    int b      = blk / (Eh / 16);
    int echunk = blk % (Eh / 16);
    int seg = threadIdx.x >> 4;
    int n   = threadIdx.x & 15;
    int e   = echunk * 16 + seg;

    float An = -expf(A_log[e * Nst + n]);
    float Dp = Dskip[e];
    float s  = 0.f;
    size_t rowbase = (size_t)b * Ll;

    for (int l = 0; l < Ll; ++l) {
        size_t row = rowbase + l;
        float dt = dtb[row * Eh + e];
        float u  = ub [row * Eh + e];
        float Bv = ssm[row * SSMW + DTRW + n];
        float Cv = ssm[row * SSMW + DTRW + Nst + n];

        s = s * __expf(dt * An) + dt * Bv * u;
        float y = s * Cv;
        y += __shfl_xor_sync(0xffffffffu, y, 1, 16);
        y += __shfl_xor_sync(0xffffffffu, y, 2, 16);
        y += __shfl_xor_sync(0xffffffffu, y, 4, 16);
        y += __shfl_xor_sync(0xffffffffu, y, 8, 16);
        if (n == 0) {
            float g = proj[row * (2 * Eh) + Eh + e];
            float sg = g / (1.f + __expf(-g));            // silu(gate)
            yb[row * Eh + e] = (y + u * Dp) * sg;
        }
    }
}

// ---------------- driver ----------------
extern "C" void kernel_launch(void* const* d_in, const int* in_sizes, int n_in,
                              void* d_out, int out_size)
{
    const float* x       = (const float*)d_in[0];
    const float* norm_w  = (const float*)d_in[1];
    const float* in_w    = (const float*)d_in[2];
    const float* conv_w  = (const float*)d_in[3];
    const float* conv_b  = (const float*)d_in[4];
    const float* xproj_w = (const float*)d_in[5];
    const float* dt_w    = (const float*)d_in[6];
    const float* dt_b    = (const float*)d_in[7];
    const float* A_log   = (const float*)d_in[8];
    const float* D_skip  = (const float*)d_in[9];
    const float* out_w   = (const float*)d_in[10];
    const float* final_w = (const float*)d_in[11];

    float *h, *hn, *proj, *u, *ssm, *dt, *y;
    cudaGetSymbolAddress((void**)&h,    g_h);
    cudaGetSymbolAddress((void**)&hn,   g_hn);
    cudaGetSymbolAddress((void**)&proj, g_proj);
    cudaGetSymbolAddress((void**)&u,    g_u);
    cudaGetSymbolAddress((void**)&ssm,  g_ssm);
    cudaGetSymbolAddress((void**)&dt,   g_dt);
    cudaGetSymbolAddress((void**)&y,    g_y);

    copy_kernel<<<(ROWS * Dh + 255) / 256, 256>>>(x, h, ROWS * Dh);

    for (int l = 0; l < NLAYERS; ++l) {
        // 1. rmsnorm
        rmsnorm_kernel<<<ROWS, 256>>>(h, norm_w + (size_t)l * Dh, hn);

        // 2. in_proj: (4096,768) x (3072,768)^T
        {
            dim3 grid((2 * Eh) / BN, ROWS / BM);
            gemm_nt<<<grid, 256>>>(hn, Dh, in_w + (size_t)l * 2 * Eh * Dh,
                                   nullptr, proj, ROWS, 2 * Eh, Dh, 0);
        }

        // 3. conv + silu
        conv_silu_kernel<<<(ROWS * Eh + 255) / 256, 256>>>(
            proj, conv_w + (size_t)l * Eh * KC, conv_b + (size_t)l * Eh, u);

        // 4. x_proj: (4096,1536) x (80,1536)^T
        {
            dim3 grid((SSMW + BN - 1) / BN, ROWS / BM);
            gemm_nt<<<grid, 256>>>(u, Eh, xproj_w + (size_t)l * SSMW * Eh,
                                   nullptr, ssm, ROWS, SSMW, Eh, 0);
        }

        // 5. dt_proj + bias + softplus: (4096,48[lda=80]) x (1536,48)^T
        {
            dim3 grid(Eh / BN, ROWS / BM);
            gemm_nt<<<grid, 256>>>(ssm, SSMW, dt_w + (size_t)l * Eh * DTRW,
                                   dt_b + (size_t)l * Eh, dt, ROWS, Eh, DTRW, 2);
        }

        // 6. selective scan + gate + D skip
        scan_kernel<<<Bb * Eh / 16, 256>>>(
            dt, u, ssm, proj,
            A_log + (size_t)l * Eh * Nst, D_skip + (size_t)l * Eh, y);

        // 7. out_proj + residual: (4096,1536) x (768,1536)^T + h
        {
            dim3 grid(Dh / BN, ROWS / BM);
            gemm_nt<<<grid, 256>>>(y, Eh, out_w + (size_t)l * Dh * Eh,
                                   h, h, ROWS, Dh, Eh, 1);
        }
    }

    // final rmsnorm -> out
    rmsnorm_kernel<<<ROWS, 256>>>(h, final_w, (float*)d_out);
}

// round 5
// speedup vs baseline: 1.2155x; 1.2155x over previous
#include <cuda_runtime.h>
#include <cuda_bf16.h>
#include <math.h>
#include <stdint.h>

// ---------------- problem constants ----------------
#define NLAYERS 8
#define Dh      768
#define Eh      1536
#define Nst     16
#define KC      4
#define DTRW    48
#define Bb      2
#define Ll      2048
#define ROWS    (Bb*Ll)          // 4096
#define SSMW    (DTRW + 2*Nst)   // 80
#define EPSV    1e-5f

// ---------------- scratch (static device, no allocs) ----------------
__device__ float g_h   [ROWS*Dh];
__device__ float g_hn  [ROWS*Dh];
__device__ float g_proj[ROWS*2*Eh];
__device__ float g_u   [ROWS*Eh];
__device__ float g_ssm [ROWS*SSMW];
__device__ float g_dt  [ROWS*Eh];
__device__ float g_y   [ROWS*Eh];

// ---------------- helpers ----------------
__device__ __forceinline__ uint32_t smem_u32(const void* p) {
    uint32_t a;
    asm("{ .reg .u64 t; cvta.to.shared.u64 t, %1; cvt.u32.u64 %0, t; }" : "=r"(a) : "l"(p));
    return a;
}
__device__ __forceinline__ uint32_t pack_bf16x2(float lo, float hi) {
    uint32_t r;
    asm("cvt.rn.satfinite.bf16x2.f32 %0, %1, %2;" : "=r"(r) : "f"(hi), "f"(lo));
    return r;
}
__device__ __forceinline__ void sts_v2(uint32_t addr, uint32_t a, uint32_t b) {
    asm volatile("st.shared.v2.b32 [%0], {%1, %2};" :: "r"(addr), "r"(a), "r"(b) : "memory");
}

#define LDSM4(R, addr) \
    asm volatile("ldmatrix.sync.aligned.m8n8.x4.shared.b16 {%0,%1,%2,%3}, [%4];" \
                 : "=r"((R)[0]), "=r"((R)[1]), "=r"((R)[2]), "=r"((R)[3]) : "r"(addr))
#define LDSM2(R, addr) \
    asm volatile("ldmatrix.sync.aligned.m8n8.x2.shared.b16 {%0,%1}, [%2];" \
                 : "=r"((R)[0]), "=r"((R)[1]) : "r"(addr))

#define MMA_BF16(Cacc, Afrag, b0, b1) \
    asm volatile("mma.sync.aligned.m16n8k16.row.col.f32.bf16.bf16.f32 " \
                 "{%0,%1,%2,%3},{%4,%5,%6,%7},{%8,%9},{%0,%1,%2,%3};" \
                 : "+f"((Cacc)[0]), "+f"((Cacc)[1]), "+f"((Cacc)[2]), "+f"((Cacc)[3]) \
                 : "r"((Afrag)[0]), "r"((Afrag)[1]), "r"((Afrag)[2]), "r"((Afrag)[3]), \
                   "r"(b0), "r"(b1))

// ================= tensor-core (mma.sync) split-bf16 GEMM =================
// C[m,n] = sum_k A[m,k]*B[n,k]; A (4096,Kd) ld=lda; B (N,Kd) ld=Kd
// mode 0: store; mode 1: += extra[m*ldc+n]; mode 2: softplus(acc + extra[n])
#define BMt 128
#define BNt 128
#define BKt 32
#define PADE 40                       // padded elems per smem row
#define TILEB (128*PADE*2)            // bytes per bf16 tile: 10240
#define STAGEB (4*TILEB)              // A_hi A_lo B_hi B_lo: 40960
#define GSMEM (2*STAGEB)              // 81920

__global__ void __launch_bounds__(256, 1) gemm_mma(
    const float* __restrict__ A, int lda,
    const float* __restrict__ Bw,
    const float* __restrict__ extra,
    float* __restrict__ C,
    int N, int Kd, int ldc, int mode)
{
    extern __shared__ __align__(16) char smraw[];
    uint32_t sb = smem_u32(smraw);

    int tid  = threadIdx.x;
    int lane = tid & 31;
    int w    = tid >> 5;
    int wm   = (w >> 2) * 64;        // warp m origin (0/64)
    int wn   = (w & 3) * 32;         // warp n origin (0/32/64/96)
    int bm = blockIdx.y * BMt;
    int bn = blockIdx.x * BNt;

    float acc[4][4][4];
    #pragma unroll
    for (int a = 0; a < 4; a++)
        #pragma unroll
        for (int b = 0; b < 4; b++)
            #pragma unroll
            for (int c = 0; c < 4; c++) acc[a][b][c] = 0.f;

    int kc = (Kd + BKt - 1) / BKt;

    float4 pa[4], pb[4];
    // per-thread loader coordinates: idx = i*256+tid; r=idx>>3, c4=idx&7
    auto loadA = [&](int c) {
        int k0 = c * BKt;
        #pragma unroll
        for (int i = 0; i < 4; ++i) {
            int idx = i * 256 + tid;
            int r = idx >> 3, c4 = idx & 7;
            int gk = k0 + c4 * 4;
            pa[i] = (gk < Kd) ? *(const float4*)(A + (size_t)(bm + r) * lda + gk)
                              : make_float4(0.f, 0.f, 0.f, 0.f);
        }
    };
    auto loadB = [&](int c) {
        int k0 = c * BKt;
        #pragma unroll
        for (int i = 0; i < 4; ++i) {
            int idx = i * 256 + tid;
            int r = idx >> 3, c4 = idx & 7;
            int gk = k0 + c4 * 4;
            pb[i] = (bn + r < N && gk < Kd)
                  ? *(const float4*)(Bw + (size_t)(bn + r) * Kd + gk)
                  : make_float4(0.f, 0.f, 0.f, 0.f);
        }
    };
    auto stash = [&](int s) {
        uint32_t stb = sb + (uint32_t)s * STAGEB;
        #pragma unroll
        for (int i = 0; i < 4; ++i) {
            int idx = i * 256 + tid;
            int r = idx >> 3, c4 = idx & 7;
            uint32_t off = (uint32_t)(r * (PADE * 2) + c4 * 8);
            // A
            {
                float4 v = pa[i];
                uint32_t h01 = pack_bf16x2(v.x, v.y);
                uint32_t h23 = pack_bf16x2(v.z, v.w);
                float hx = __uint_as_float(h01 << 16);
                float hy = __uint_as_float(h01 & 0xFFFF0000u);
                float hz = __uint_as_float(h23 << 16);
                float hw = __uint_as_float(h23 & 0xFFFF0000u);
                uint32_t l01 = pack_bf16x2(v.x - hx, v.y - hy);
                uint32_t l23 = pack_bf16x2(v.z - hz, v.w - hw);
                sts_v2(stb + off, h01, h23);
                sts_v2(stb + TILEB + off, l01, l23);
            }
            // B
            {
                float4 v = pb[i];
                uint32_t h01 = pack_bf16x2(v.x, v.y);
                uint32_t h23 = pack_bf16x2(v.z, v.w);
                float hx = __uint_as_float(h01 << 16);
                float hy = __uint_as_float(h01 & 0xFFFF0000u);
                float hz = __uint_as_float(h23 << 16);
                float hw = __uint_as_float(h23 & 0xFFFF0000u);
                uint32_t l01 = pack_bf16x2(v.x - hx, v.y - hy);
                uint32_t l23 = pack_bf16x2(v.z - hz, v.w - hw);
                sts_v2(stb + 2 * TILEB + off, h01, h23);
                sts_v2(stb + 3 * TILEB + off, l01, l23);
            }
        }
    };

    loadA(0); loadB(0);
    stash(0);
    __syncthreads();

    for (int c = 0; c < kc; ++c) {
        int s = c & 1;
        if (c + 1 < kc) { loadA(c + 1); loadB(c + 1); }

        uint32_t stb = sb + (uint32_t)s * STAGEB;
        // fragment smem addresses (invariant parts)
        int arow = wm + (lane & 15);
        int acol = (lane >> 4) << 3;
        int brow = wn + (lane & 7);
        int bcol = ((lane >> 3) & 1) << 3;

        #pragma unroll
        for (int ks = 0; ks < 2; ++ks) {
            int kk = ks * 16;
            uint32_t ah[4][4], al[4][4], bh[4][2], bl[4][2];
            #pragma unroll
            for (int mt = 0; mt < 4; ++mt) {
                uint32_t ad = stb + (uint32_t)((arow + mt * 16) * (PADE * 2) + (acol + kk) * 2);
                LDSM4(ah[mt], ad);
                LDSM4(al[mt], ad + TILEB);
            }
            #pragma unroll
            for (int nt = 0; nt < 4; ++nt) {
                uint32_t bd = stb + 2 * TILEB
                            + (uint32_t)((brow + nt * 8) * (PADE * 2) + (bcol + kk) * 2);
                LDSM2(bh[nt], bd);
                LDSM2(bl[nt], bd + TILEB);
            }
            #pragma unroll
            for (int mt = 0; mt < 4; ++mt)
                #pragma unroll
                for (int nt = 0; nt < 4; ++nt) {
                    MMA_BF16(acc[mt][nt], ah[mt], bh[nt][0], bh[nt][1]);
                    MMA_BF16(acc[mt][nt], ah[mt], bl[nt][0], bl[nt][1]);
                    MMA_BF16(acc[mt][nt], al[mt], bh[nt][0], bh[nt][1]);
                }
        }
        __syncthreads();
        if (c + 1 < kc) {
            stash((c + 1) & 1);
            __syncthreads();
        }
    }

    // ---------------- epilogue ----------------
    #pragma unroll
    for (int mt = 0; mt < 4; ++mt) {
        #pragma unroll
        for (int half = 0; half < 2; ++half) {
            int m = bm + wm + mt * 16 + (lane >> 2) + half * 8;
            #pragma unroll
            for (int nt = 0; nt < 4; ++nt) {
                int n = bn + wn + nt * 8 + (lane & 3) * 2;
                if (n < N) {
                    float v0 = acc[mt][nt][half * 2 + 0];
                    float v1 = acc[mt][nt][half * 2 + 1];
                    if (mode == 1) {
                        const float* e = extra + (size_t)m * ldc + n;
                        v0 += e[0]; v1 += e[1];
                    } else if (mode == 2) {
                        v0 += extra[n]; v1 += extra[n + 1];
                        v0 = (v0 > 20.f) ? v0 : log1pf(expf(v0));
                        v1 = (v1 > 20.f) ? v1 : log1pf(expf(v1));
                    }
                    *(float2*)(C + (size_t)m * ldc + n) = make_float2(v0, v1);
                }
            }
        }
    }
}

// ---------------- small kernels ----------------
__global__ void copy_kernel(const float* __restrict__ src, float* __restrict__ dst, int n) {
    int i = blockIdx.x * 256 + threadIdx.x;
    if (i < n) dst[i] = src[i];
}

__global__ void __launch_bounds__(256) rmsnorm_kernel(
    const float* __restrict__ x, const float* __restrict__ w, float* __restrict__ out)
{
    __shared__ float sh[8];
    int row = blockIdx.x;
    const float* xr = x + (size_t)row * Dh;
    float s = 0.f;
    #pragma unroll
    for (int i = threadIdx.x; i < Dh; i += 256) { float v = xr[i]; s += v * v; }
    #pragma unroll
    for (int o = 16; o; o >>= 1) s += __shfl_xor_sync(0xffffffffu, s, o);
    int wid = threadIdx.x >> 5, lane = threadIdx.x & 31;
    if (lane == 0) sh[wid] = s;
    __syncthreads();
    if (wid == 0) {
        float v = (lane < 8) ? sh[lane] : 0.f;
        #pragma unroll
        for (int o = 4; o; o >>= 1) v += __shfl_xor_sync(0xffffffffu, v, o);
        if (lane == 0) sh[0] = rsqrtf(v * (1.f / Dh) + EPSV);
    }
    __syncthreads();
    float rs = sh[0];
    #pragma unroll
    for (int i = threadIdx.x; i < Dh; i += 256)
        out[(size_t)row * Dh + i] = xr[i] * rs * w[i];
}

__global__ void conv_silu_kernel(
    const float* __restrict__ proj,
    const float* __restrict__ cw,
    const float* __restrict__ cb,
    float* __restrict__ out)
{
    int idx = blockIdx.x * 256 + threadIdx.x;
    if (idx >= ROWS * Eh) return;
    int e  = idx % Eh;
    int bl = idx / Eh;
    int l  = bl % Ll;
    float acc = cb[e];
    #pragma unroll
    for (int k = 0; k < KC; ++k) {
        int ls = l - (KC - 1) + k;
        if (ls >= 0)
            acc += cw[e * KC + k] * proj[(size_t)(bl + ls - l) * (2 * Eh) + e];
    }
    out[(size_t)bl * Eh + e] = acc / (1.f + __expf(-acc));
}

__global__ void __launch_bounds__(256) scan_kernel(
    const float* __restrict__ dtb,
    const float* __restrict__ ub,
    const float* __restrict__ ssm,
    const float* __restrict__ proj,
    const float* __restrict__ A_log,
    const float* __restrict__ Dskip,
    float* __restrict__ yb)
{
    int blk = blockIdx.x;
    int b      = blk / (Eh / 16);
    int echunk = blk % (Eh / 16);
    int seg = threadIdx.x >> 4;
    int n   = threadIdx.x & 15;
    int e   = echunk * 16 + seg;

    float An = -expf(A_log[e * Nst + n]);
    float Dp = Dskip[e];
    float s  = 0.f;
    size_t rowbase = (size_t)b * Ll;

    for (int l = 0; l < Ll; ++l) {
        size_t row = rowbase + l;
        float dt = dtb[row * Eh + e];
        float u  = ub [row * Eh + e];
        float Bv = ssm[row * SSMW + DTRW + n];
        float Cv = ssm[row * SSMW + DTRW + Nst + n];

        s = s * __expf(dt * An) + dt * Bv * u;
        float y = s * Cv;
        y += __shfl_xor_sync(0xffffffffu, y, 1, 16);
        y += __shfl_xor_sync(0xffffffffu, y, 2, 16);
        y += __shfl_xor_sync(0xffffffffu, y, 4, 16);
        y += __shfl_xor_sync(0xffffffffu, y, 8, 16);
        if (n == 0) {
            float g = proj[row * (2 * Eh) + Eh + e];
            float sg = g / (1.f + __expf(-g));
            yb[row * Eh + e] = (y + u * Dp) * sg;
        }
    }
}

// ---------------- driver ----------------
extern "C" void kernel_launch(void* const* d_in, const int* in_sizes, int n_in,
                              void* d_out, int out_size)
{
    const float* x       = (const float*)d_in[0];
    const float* norm_w  = (const float*)d_in[1];
    const float* in_w    = (const float*)d_in[2];
    const float* conv_w  = (const float*)d_in[3];
    const float* conv_b  = (const float*)d_in[4];
    const float* xproj_w = (const float*)d_in[5];
    const float* dt_w    = (const float*)d_in[6];
    const float* dt_b    = (const float*)d_in[7];
    const float* A_log   = (const float*)d_in[8];
    const float* D_skip  = (const float*)d_in[9];
    const float* out_w   = (const float*)d_in[10];
    const float* final_w = (const float*)d_in[11];

    float *h, *hn, *proj, *u, *ssm, *dt, *y;
    cudaGetSymbolAddress((void**)&h,    g_h);
    cudaGetSymbolAddress((void**)&hn,   g_hn);
    cudaGetSymbolAddress((void**)&proj, g_proj);
    cudaGetSymbolAddress((void**)&u,    g_u);
    cudaGetSymbolAddress((void**)&ssm,  g_ssm);
    cudaGetSymbolAddress((void**)&dt,   g_dt);
    cudaGetSymbolAddress((void**)&y,    g_y);

    cudaFuncSetAttribute(gemm_mma, cudaFuncAttributeMaxDynamicSharedMemorySize, GSMEM);

    copy_kernel<<<(ROWS * Dh + 255) / 256, 256>>>(x, h, ROWS * Dh);

    for (int l = 0; l < NLAYERS; ++l) {
        rmsnorm_kernel<<<ROWS, 256>>>(h, norm_w + (size_t)l * Dh, hn);

        // in_proj: (4096,768) x (3072,768)^T -> proj
        {
            dim3 grid((2 * Eh + BNt - 1) / BNt, ROWS / BMt);
            gemm_mma<<<grid, 256, GSMEM>>>(hn, Dh, in_w + (size_t)l * 2 * Eh * Dh,
                                           nullptr, proj, 2 * Eh, Dh, 2 * Eh, 0);
        }

        conv_silu_kernel<<<(ROWS * Eh + 255) / 256, 256>>>(
            proj, conv_w + (size_t)l * Eh * KC, conv_b + (size_t)l * Eh, u);

        // x_proj: (4096,1536) x (80,1536)^T -> ssm
        {
            dim3 grid((SSMW + BNt - 1) / BNt, ROWS / BMt);
            gemm_mma<<<grid, 256, GSMEM>>>(u, Eh, xproj_w + (size_t)l * SSMW * Eh,
                                           nullptr, ssm, SSMW, Eh, SSMW, 0);
        }

        // dt_proj + bias + softplus: (4096,48 ld=80) x (1536,48)^T -> dt
        {
            dim3 grid((Eh + BNt - 1) / BNt, ROWS / BMt);
            gemm_mma<<<grid, 256, GSMEM>>>(ssm, SSMW, dt_w + (size_t)l * Eh * DTRW,
                                           dt_b + (size_t)l * Eh, dt, Eh, DTRW, Eh, 2);
        }

        scan_kernel<<<Bb * Eh / 16, 256>>>(
            dt, u, ssm, proj,
            A_log + (size_t)l * Eh * Nst, D_skip + (size_t)l * Eh, y);

        // out_proj + residual: (4096,1536) x (768,1536)^T + h -> h
        {
            dim3 grid((Dh + BNt - 1) / BNt, ROWS / BMt);
            gemm_mma<<<grid, 256, GSMEM>>>(y, Eh, out_w + (size_t)l * Dh * Eh,
                                           h, h, Dh, Eh, Dh, 1);
        }
    }

    rmsnorm_kernel<<<ROWS, 256>>>(h, final_w, (float*)d_out);
}

// round 8
// speedup vs baseline: 3.2199x; 2.6490x over previous
#include <cuda_runtime.h>
#include <cuda_bf16.h>
#include <math.h>
#include <stdint.h>

// ---------------- problem constants ----------------
#define NLAYERS 8
#define Dh      768
#define Eh      1536
#define Nst     16
#define KC      4
#define DTRW    48
#define Bb      2
#define Ll      2048
#define ROWS    (Bb*Ll)          // 4096
#define SSMW    (DTRW + 2*Nst)   // 80
#define EPSV    1e-5f

// ---------------- scratch (static device, no allocs) ----------------
__device__ float g_h   [ROWS*Dh];
__device__ float g_proj[ROWS*2*Eh];
__device__ float g_u   [ROWS*Eh];
__device__ float g_ssm [ROWS*SSMW];
__device__ float g_dt  [ROWS*Eh];

__device__ __nv_bfloat16 g_hn_h[ROWS*Dh],  g_hn_l[ROWS*Dh];
__device__ __nv_bfloat16 g_u_h [ROWS*Eh],  g_u_l [ROWS*Eh];
__device__ __nv_bfloat16 g_ssm_h[ROWS*64], g_ssm_l[ROWS*64];
__device__ __nv_bfloat16 g_y_h [ROWS*Eh],  g_y_l [ROWS*Eh];

__device__ __nv_bfloat16 g_win_h [NLAYERS*2*Eh*Dh], g_win_l [NLAYERS*2*Eh*Dh];
__device__ __nv_bfloat16 g_wx_h  [NLAYERS*SSMW*Eh], g_wx_l  [NLAYERS*SSMW*Eh];
__device__ __nv_bfloat16 g_wdt_h [NLAYERS*Eh*64],   g_wdt_l [NLAYERS*Eh*64];
__device__ __nv_bfloat16 g_wout_h[NLAYERS*Dh*Eh],   g_wout_l[NLAYERS*Dh*Eh];

// ---------------- helpers ----------------
__device__ __forceinline__ uint32_t smem_u32(const void* p) {
    uint32_t a;
    asm("{ .reg .u64 t; cvta.to.shared.u64 t, %1; cvt.u32.u64 %0, t; }" : "=r"(a) : "l"(p));
    return a;
}
__device__ __forceinline__ uint32_t pack_bf16x2(float lo, float hi) {
    uint32_t r;
    asm("cvt.rn.satfinite.bf16x2.f32 %0, %1, %2;" : "=r"(r) : "f"(hi), "f"(lo));
    return r;
}
__device__ __forceinline__ void cp16(uint32_t dst, const void* src, bool v) {
    int sz = v ? 16 : 0;
    asm volatile("cp.async.cg.shared.global [%0], [%1], 16, %2;"
                 :: "r"(dst), "l"(src), "r"(sz) : "memory");
}
#define CP_COMMIT() asm volatile("cp.async.commit_group;" ::: "memory")
#define CP_WAIT1()  asm volatile("cp.async.wait_group 1;" ::: "memory")

#define LDSM4(R, addr) \
    asm volatile("ldmatrix.sync.aligned.m8n8.x4.shared.b16 {%0,%1,%2,%3}, [%4];" \
                 : "=r"((R)[0]), "=r"((R)[1]), "=r"((R)[2]), "=r"((R)[3]) : "r"(addr))
#define LDSM2(R, addr) \
    asm volatile("ldmatrix.sync.aligned.m8n8.x2.shared.b16 {%0,%1}, [%2];" \
                 : "=r"((R)[0]), "=r"((R)[1]) : "r"(addr))

#define MMA_BF16(Cacc, Afrag, b0, b1) \
    asm volatile("mma.sync.aligned.m16n8k16.row.col.f32.bf16.bf16.f32 " \
                 "{%0,%1,%2,%3},{%4,%5,%6,%7},{%8,%9},{%0,%1,%2,%3};" \
                 : "+f"((Cacc)[0]), "+f"((Cacc)[1]), "+f"((Cacc)[2]), "+f"((Cacc)[3]) \
                 : "r"((Afrag)[0]), "r"((Afrag)[1]), "r"((Afrag)[2]), "r"((Afrag)[3]), \
                   "r"(b0), "r"(b1))

// ================= split-bf16 GEMM with cp.async pipeline =================
// C[m,n] = sum_k A[m,k]*B[n,k]; A split (hi/lo bf16, ld=lda); B split (ld=Kd)
// mode 0: store fp32; mode 1: += extra[m*ldc+n]; mode 2: softplus(acc+extra[n]);
// mode 3: store fp32 + split store to Chi/Clo (ld 64, zero for n>=48)
#define BMt 128
#define BNt 128
#define BKt 32
#define TILEB 8192                  // 128 rows x 64B
#define STAGEB (4*TILEB)            // Ah Al Bh Bl
#define GSMEM (2*STAGEB)            // 65536

__global__ void __launch_bounds__(256) gemm_mma(
    const __nv_bfloat16* __restrict__ Ah_, const __nv_bfloat16* __restrict__ Al_, int lda,
    const __nv_bfloat16* __restrict__ Bh_, const __nv_bfloat16* __restrict__ Bl_,
    const float* __restrict__ extra,
    float* __restrict__ C,
    __nv_bfloat16* __restrict__ Chi, __nv_bfloat16* __restrict__ Clo,
    int N, int Kd, int ldc, int mode)
{
    extern __shared__ __align__(16) char smraw[];
    uint32_t sb = smem_u32(smraw);

    int tid = threadIdx.x, lane = tid & 31, w = tid >> 5;
    int wm = (w >> 2) * 64, wn = (w & 3) * 32;
    int bm = blockIdx.y * BMt, bn = blockIdx.x * BNt;

    float acc[4][4][4];
    #pragma unroll
    for (int a = 0; a < 4; a++)
        #pragma unroll
        for (int b = 0; b < 4; b++)
            #pragma unroll
            for (int c = 0; c < 4; c++) acc[a][b][c] = 0.f;

    int kc = Kd / BKt;

    auto prefetch = [&](int c) {
        int s = c & 1;
        uint32_t stb = sb + (uint32_t)s * STAGEB;
        int k0 = c * BKt;
        #pragma unroll
        for (int i = 0; i < 2; ++i) {
            int idx = tid * 2 + i;          // 0..511
            int r = idx >> 2, c4 = idx & 3;
            uint32_t sw = (uint32_t)(r * 64 + ((c4 ^ ((r >> 1) & 3)) << 4));
            const __nv_bfloat16* a_h = Ah_ + (size_t)(bm + r) * lda + k0 + c4 * 8;
            const __nv_bfloat16* a_l = Al_ + (size_t)(bm + r) * lda + k0 + c4 * 8;
            cp16(stb + sw, a_h, true);
            cp16(stb + TILEB + sw, a_l, true);
            bool bv = (bn + r) < N;
            size_t brow = bv ? (size_t)(bn + r) : 0;
            cp16(stb + 2 * TILEB + sw, Bh_ + brow * Kd + k0 + c4 * 8, bv);
            cp16(stb + 3 * TILEB + sw, Bl_ + brow * Kd + k0 + c4 * 8, bv);
        }
        CP_COMMIT();
    };

    prefetch(0);
    if (kc > 1) prefetch(1); else CP_COMMIT();

    for (int c = 0; c < kc; ++c) {
        CP_WAIT1();
        __syncthreads();
        uint32_t stb = sb + (uint32_t)(c & 1) * STAGEB;
        int arow = wm + (lane & 15);
        int acol = (lane >> 4) << 3;
        int brow = wn + (lane & 7);
        int bcol = ((lane >> 3) & 1) << 3;

        #pragma unroll
        for (int ks = 0; ks < 2; ++ks) {
            int kk = ks * 16;
            uint32_t ahf[4][4], alf[4][4], bhf[4][2], blf[4][2];
            #pragma unroll
            for (int mt = 0; mt < 4; ++mt) {
                int row = arow + mt * 16;
                int j = (acol + kk) >> 3;
                uint32_t ad = stb + (uint32_t)(row * 64 + ((j ^ ((row >> 1) & 3)) << 4));
                LDSM4(ahf[mt], ad);
                LDSM4(alf[mt], ad + TILEB);
            }
            #pragma unroll
            for (int nt = 0; nt < 4; ++nt) {
                int row = brow + nt * 8;
                int j = (bcol + kk) >> 3;
                uint32_t bd = stb + 2 * TILEB
                            + (uint32_t)(row * 64 + ((j ^ ((row >> 1) & 3)) << 4));
                LDSM2(bhf[nt], bd);
                LDSM2(blf[nt], bd + TILEB);
            }
            #pragma unroll
            for (int mt = 0; mt < 4; ++mt)
                #pragma unroll
                for (int nt = 0; nt < 4; ++nt) {
                    MMA_BF16(acc[mt][nt], ahf[mt], bhf[nt][0], bhf[nt][1]);
                    MMA_BF16(acc[mt][nt], ahf[mt], blf[nt][0], blf[nt][1]);
                    MMA_BF16(acc[mt][nt], alf[mt], bhf[nt][0], bhf[nt][1]);
                }
        }
        __syncthreads();
        if (c + 2 < kc) prefetch(c + 2); else CP_COMMIT();
    }

    // ---------------- epilogue ----------------
    #pragma unroll
    for (int mt = 0; mt < 4; ++mt) {
        #pragma unroll
        for (int half = 0; half < 2; ++half) {
            int m = bm + wm + mt * 16 + (lane >> 2) + half * 8;
            #pragma unroll
            for (int nt = 0; nt < 4; ++nt) {
                int n = bn + wn + nt * 8 + (lane & 3) * 2;
                float v0 = acc[mt][nt][half * 2 + 0];
                float v1 = acc[mt][nt][half * 2 + 1];
                if (mode == 1) {
                    const float* e = extra + (size_t)m * ldc + n;
                    v0 += e[0]; v1 += e[1];
                } else if (mode == 2) {
                    v0 += extra[n]; v1 += extra[n + 1];
                    v0 = (v0 > 20.f) ? v0 : log1pf(expf(v0));
                    v1 = (v1 > 20.f) ? v1 : log1pf(expf(v1));
                }
                if (n < N)
                    *(float2*)(C + (size_t)m * ldc + n) = make_float2(v0, v1);
                if (mode == 3 && n < 64) {
                    float a0 = (n < 48) ? v0 : 0.f;
                    float a1 = (n + 1 < 48) ? v1 : 0.f;
                    uint32_t hp = pack_bf16x2(a0, a1);
                    float f0 = __uint_as_float(hp << 16);
                    float f1 = __uint_as_float(hp & 0xFFFF0000u);
                    uint32_t lp = pack_bf16x2(a0 - f0, a1 - f1);
                    *(uint32_t*)(Chi + (size_t)m * 64 + n) = hp;
                    *(uint32_t*)(Clo + (size_t)m * 64 + n) = lp;
                }
            }
        }
    }
}

// ---------------- weight / activation split ----------------
__global__ void split_kernel(const float* __restrict__ src,
                             __nv_bfloat16* __restrict__ dh,
                             __nv_bfloat16* __restrict__ dl,
                             int rows, int cs, int cd)
{
    int idx = blockIdx.x * 256 + threadIdx.x;
    if (idx >= rows * cd) return;
    int r = idx / cd, c = idx - r * cd;
    float v = (c < cs) ? src[(size_t)r * cs + c] : 0.f;
    __nv_bfloat16 h = __float2bfloat16(v);
    dh[idx] = h;
    dl[idx] = __float2bfloat16(v - __bfloat162float(h));
}

// ---------------- small kernels ----------------
__global__ void copy_kernel(const float* __restrict__ src, float* __restrict__ dst, int n) {
    int i = blockIdx.x * 256 + threadIdx.x;
    if (i < n) dst[i] = src[i];
}

// rmsnorm: writes fp32 (if outf) else split bf16
__global__ void __launch_bounds__(256) rmsnorm_kernel(
    const float* __restrict__ x, const float* __restrict__ w,
    float* __restrict__ outf,
    __nv_bfloat16* __restrict__ oh, __nv_bfloat16* __restrict__ ol)
{
    __shared__ float sh[8];
    int row = blockIdx.x;
    const float* xr = x + (size_t)row * Dh;
    float s = 0.f;
    #pragma unroll
    for (int i = threadIdx.x; i < Dh; i += 256) { float v = xr[i]; s += v * v; }
    #pragma unroll
    for (int o = 16; o; o >>= 1) s += __shfl_xor_sync(0xffffffffu, s, o);
    int wid = threadIdx.x >> 5, lane = threadIdx.x & 31;
    if (lane == 0) sh[wid] = s;
    __syncthreads();
    if (wid == 0) {
        float v = (lane < 8) ? sh[lane] : 0.f;
        #pragma unroll
        for (int o = 4; o; o >>= 1) v += __shfl_xor_sync(0xffffffffu, v, o);
        if (lane == 0) sh[0] = rsqrtf(v * (1.f / Dh) + EPSV);
    }
    __syncthreads();
    float rs = sh[0];
    #pragma unroll
    for (int i = threadIdx.x; i < Dh; i += 256) {
        float v = xr[i] * rs * w[i];
        size_t o = (size_t)row * Dh + i;
        if (outf) outf[o] = v;
        else {
            __nv_bfloat16 h = __float2bfloat16(v);
            oh[o] = h;
            ol[o] = __float2bfloat16(v - __bfloat162float(h));
        }
    }
}

// causal depthwise conv + bias + silu; writes fp32 u + split
__global__ void conv_silu_kernel(
    const float* __restrict__ proj,
    const float* __restrict__ cw,
    const float* __restrict__ cb,
    float* __restrict__ out,
    __nv_bfloat16* __restrict__ oh, __nv_bfloat16* __restrict__ ol)
{
    int idx = blockIdx.x * 256 + threadIdx.x;
    if (idx >= ROWS * Eh) return;
    int e  = idx % Eh;
    int bl = idx / Eh;
    int l  = bl % Ll;
    float acc = cb[e];
    #pragma unroll
    for (int k = 0; k < KC; ++k) {
        int ls = l - (KC - 1) + k;
        if (ls >= 0)
            acc += cw[e * KC + k] * proj[(size_t)(bl + ls - l) * (2 * Eh) + e];
    }
    float v = acc / (1.f + __expf(-acc));
    size_t o = (size_t)bl * Eh + e;
    out[o] = v;
    __nv_bfloat16 h = __float2bfloat16(v);
    oh[o] = h;
    ol[o] = __float2bfloat16(v - __bfloat162float(h));
}

// ---------------- selective scan v2: smem-staged, interleaved shfl ----------------
__global__ void __launch_bounds__(128) scan_kernel(
    const float* __restrict__ dtb,
    const float* __restrict__ ub,
    const float* __restrict__ ssm,
    const float* __restrict__ proj,
    const float* __restrict__ A_log,
    const float* __restrict__ Dskip,
    __nv_bfloat16* __restrict__ yh, __nv_bfloat16* __restrict__ yl)
{
    __shared__ float sdt[64][8], su[64][8], sg[64][8], sB[64][16], sC[64][16];
    int tid = threadIdx.x;
    int blk = blockIdx.x;
    int b   = blk / (Eh / 8);
    int e0  = (blk % (Eh / 8)) * 8;
    int seg = tid >> 4, n = tid & 15;
    int e = e0 + seg;

    float An = -expf(A_log[e * Nst + n]);
    float Dp = Dskip[e];
    float s  = 0.f;
    size_t rowbase = (size_t)b * Ll;

    int t  = tid >> 1, hf = tid & 1;
    int tq = tid >> 2, q  = tid & 3;

    for (int c0 = 0; c0 < Ll; c0 += 64) {
        {
            size_t row = rowbase + c0 + t;
            float4 v;
            v = *(const float4*)(dtb + row * Eh + e0 + hf * 4);
            *(float4*)&sdt[t][hf * 4] = v;
            v = *(const float4*)(ub + row * Eh + e0 + hf * 4);
            *(float4*)&su[t][hf * 4] = v;
            v = *(const float4*)(proj + row * (size_t)(2 * Eh) + Eh + e0 + hf * 4);
            *(float4*)&sg[t][hf * 4] = v;
            #pragma unroll
            for (int hh = 0; hh < 2; ++hh) {
                int tt = tq + hh * 32;
                size_t r2 = rowbase + c0 + tt;
                float4 vb = *(const float4*)(ssm + r2 * SSMW + DTRW + q * 4);
                *(float4*)&sB[tt][q * 4] = vb;
                float4 vc = *(const float4*)(ssm + r2 * SSMW + DTRW + Nst + q * 4);
                *(float4*)&sC[tt][q * 4] = vc;
            }
        }
        __syncthreads();

        for (int tt = 0; tt < 64; tt += 2) {
            float dt0 = sdt[tt][seg],   u0 = su[tt][seg];
            float s0 = s * __expf(dt0 * An) + dt0 * sB[tt][n] * u0;
            float y0 = s0 * sC[tt][n];
            float dt1 = sdt[tt + 1][seg], u1 = su[tt + 1][seg];
            float s1 = s0 * __expf(dt1 * An) + dt1 * sB[tt + 1][n] * u1;
            float y1 = s1 * sC[tt + 1][n];
            s = s1;
            y0 += __shfl_xor_sync(0xffffffffu, y0, 1, 16);
            y1 += __shfl_xor_sync(0xffffffffu, y1, 1, 16);
            y0 += __shfl_xor_sync(0xffffffffu, y0, 2, 16);
            y1 += __shfl_xor_sync(0xffffffffu, y1, 2, 16);
            y0 += __shfl_xor_sync(0xffffffffu, y0, 4, 16);
            y1 += __shfl_xor_sync(0xffffffffu, y1, 4, 16);
            y0 += __shfl_xor_sync(0xffffffffu, y0, 8, 16);
            y1 += __shfl_xor_sync(0xffffffffu, y1, 8, 16);
            if (n == 0) {
                size_t row = rowbase + c0 + tt;
                float g0 = sg[tt][seg];
                float o0 = (y0 + u0 * Dp) * (g0 / (1.f + __expf(-g0)));
                float g1 = sg[tt + 1][seg];
                float o1 = (y1 + u1 * Dp) * (g1 / (1.f + __expf(-g1)));
                __nv_bfloat16 h0 = __float2bfloat16(o0);
                yh[row * Eh + e] = h0;
                yl[row * Eh + e] = __float2bfloat16(o0 - __bfloat162float(h0));
                __nv_bfloat16 h1 = __float2bfloat16(o1);
                yh[(row + 1) * Eh + e] = h1;
                yl[(row + 1) * Eh + e] = __float2bfloat16(o1 - __bfloat162float(h1));
            }
        }
        __syncthreads();
    }
}

// ---------------- driver ----------------
extern "C" void kernel_launch(void* const* d_in, const int* in_sizes, int n_in,
                              void* d_out, int out_size)
{
    const float* x       = (const float*)d_in[0];
    const float* norm_w  = (const float*)d_in[1];
    const float* in_w    = (const float*)d_in[2];
    const float* conv_w  = (const float*)d_in[3];
    const float* conv_b  = (const float*)d_in[4];
    const float* xproj_w = (const float*)d_in[5];
    const float* dt_w    = (const float*)d_in[6];
    const float* dt_b    = (const float*)d_in[7];
    const float* A_log   = (const float*)d_in[8];
    const float* D_skip  = (const float*)d_in[9];
    const float* out_w   = (const float*)d_in[10];
    const float* final_w = (const float*)d_in[11];

    float *h, *proj, *u, *ssm, *dt;
    __nv_bfloat16 *hn_h, *hn_l, *u_h, *u_l, *ssm_h, *ssm_l, *y_h, *y_l;
    __nv_bfloat16 *win_h, *win_l, *wx_h, *wx_l, *wdt_h, *wdt_l, *wout_h, *wout_l;
    cudaGetSymbolAddress((void**)&h,    g_h);
    cudaGetSymbolAddress((void**)&proj, g_proj);
    cudaGetSymbolAddress((void**)&u,    g_u);
    cudaGetSymbolAddress((void**)&ssm,  g_ssm);
    cudaGetSymbolAddress((void**)&dt,   g_dt);
    cudaGetSymbolAddress((void**)&hn_h, g_hn_h);  cudaGetSymbolAddress((void**)&hn_l, g_hn_l);
    cudaGetSymbolAddress((void**)&u_h,  g_u_h);   cudaGetSymbolAddress((void**)&u_l,  g_u_l);
    cudaGetSymbolAddress((void**)&ssm_h,g_ssm_h); cudaGetSymbolAddress((void**)&ssm_l,g_ssm_l);
    cudaGetSymbolAddress((void**)&y_h,  g_y_h);   cudaGetSymbolAddress((void**)&y_l,  g_y_l);
    cudaGetSymbolAddress((void**)&win_h, g_win_h);  cudaGetSymbolAddress((void**)&win_l, g_win_l);
    cudaGetSymbolAddress((void**)&wx_h,  g_wx_h);   cudaGetSymbolAddress((void**)&wx_l,  g_wx_l);
    cudaGetSymbolAddress((void**)&wdt_h, g_wdt_h);  cudaGetSymbolAddress((void**)&wdt_l, g_wdt_l);
    cudaGetSymbolAddress((void**)&wout_h,g_wout_h); cudaGetSymbolAddress((void**)&wout_l,g_wout_l);

    cudaFuncSetAttribute(gemm_mma, cudaFuncAttributeMaxDynamicSharedMemorySize, GSMEM);

    // split all weights (per replay; ~50us)
    {
        int n1 = NLAYERS * 2 * Eh * Dh;
        split_kernel<<<(n1 + 255) / 256, 256>>>(in_w, win_h, win_l, NLAYERS * 2 * Eh, Dh, Dh);
        int n2 = NLAYERS * SSMW * Eh;
        split_kernel<<<(n2 + 255) / 256, 256>>>(xproj_w, wx_h, wx_l, NLAYERS * SSMW, Eh, Eh);
        int n3 = NLAYERS * Eh * 64;
        split_kernel<<<(n3 + 255) / 256, 256>>>(dt_w, wdt_h, wdt_l, NLAYERS * Eh, DTRW, 64);
        int n4 = NLAYERS * Dh * Eh;
        split_kernel<<<(n4 + 255) / 256, 256>>>(out_w, wout_h, wout_l, NLAYERS * Dh, Eh, Eh);
    }

    copy_kernel<<<(ROWS * Dh + 255) / 256, 256>>>(x, h, ROWS * Dh);

    for (int l = 0; l < NLAYERS; ++l) {
        rmsnorm_kernel<<<ROWS, 256>>>(h, norm_w + (size_t)l * Dh, nullptr, hn_h, hn_l);

        // in_proj -> proj (fp32)
        {
            dim3 grid(2 * Eh / BNt, ROWS / BMt);
            gemm_mma<<<grid, 256, GSMEM>>>(hn_h, hn_l, Dh,
                                           win_h + (size_t)l * 2 * Eh * Dh,
                                           win_l + (size_t)l * 2 * Eh * Dh,
                                           nullptr, proj, nullptr, nullptr,
                                           2 * Eh, Dh, 2 * Eh, 0);
        }

        conv_silu_kernel<<<(ROWS * Eh + 255) / 256, 256>>>(
            proj, conv_w + (size_t)l * Eh * KC, conv_b + (size_t)l * Eh, u, u_h, u_l);

        // x_proj -> ssm fp32 + ssm split (dt_r cols, zero-padded to 64)
        {
            dim3 grid(1, ROWS / BMt);
            gemm_mma<<<grid, 256, GSMEM>>>(u_h, u_l, Eh,
                                           wx_h + (size_t)l * SSMW * Eh,
                                           wx_l + (size_t)l * SSMW * Eh,
                                           nullptr, ssm, ssm_h, ssm_l,
                                           SSMW, Eh, SSMW, 3);
        }

        // dt_proj + softplus -> dt fp32
        {
            dim3 grid(Eh / BNt, ROWS / BMt);
            gemm_mma<<<grid, 256, GSMEM>>>(ssm_h, ssm_l, 64,
                                           wdt_h + (size_t)l * Eh * 64,
                                           wdt_l + (size_t)l * Eh * 64,
                                           dt_b + (size_t)l * Eh, dt, nullptr, nullptr,
                                           Eh, 64, Eh, 2);
        }

        scan_kernel<<<Bb * Eh / 8, 128>>>(
            dt, u, ssm, proj,
            A_log + (size_t)l * Eh * Nst, D_skip + (size_t)l * Eh, y_h, y_l);

        // out_proj + residual -> h
        {
            dim3 grid(Dh / BNt, ROWS / BMt);
            gemm_mma<<<grid, 256, GSMEM>>>(y_h, y_l, Eh,
                                           wout_h + (size_t)l * Dh * Eh,
                                           wout_l + (size_t)l * Dh * Eh,
                                           h, h, nullptr, nullptr,
                                           Dh, Eh, Dh, 1);
        }
    }

    rmsnorm_kernel<<<ROWS, 256>>>(h, final_w, (float*)d_out, nullptr, nullptr);
}

// round 10
// speedup vs baseline: 3.6053x; 1.1197x over previous
#include <cuda_runtime.h>
#include <cuda_bf16.h>
#include <math.h>
#include <stdint.h>

// ---------------- problem constants ----------------
#define NLAYERS 8
#define Dh      768
#define Eh      1536
#define Nst     16
#define KC      4
#define DTRW    48
#define Bb      2
#define Ll      2048
#define ROWS    (Bb*Ll)          // 4096
#define SSMW    (DTRW + 2*Nst)   // 80
#define EPSV    1e-5f

// ---------------- scratch (static device, no allocs) ----------------
__device__ float g_h   [ROWS*Dh];
__device__ float g_proj[ROWS*2*Eh];
__device__ float g_u   [ROWS*Eh];
__device__ float g_ssm [ROWS*SSMW];
__device__ float g_dt  [ROWS*Eh];
__device__ float g_xpart[4*ROWS*SSMW];

__device__ __nv_bfloat16 g_hn_h[ROWS*Dh],  g_hn_l[ROWS*Dh];
__device__ __nv_bfloat16 g_u_h [ROWS*Eh],  g_u_l [ROWS*Eh];
__device__ __nv_bfloat16 g_ssm_h[ROWS*64], g_ssm_l[ROWS*64];
__device__ __nv_bfloat16 g_y_h [ROWS*Eh],  g_y_l [ROWS*Eh];

__device__ __nv_bfloat16 g_win_h [NLAYERS*2*Eh*Dh], g_win_l [NLAYERS*2*Eh*Dh];
__device__ __nv_bfloat16 g_wx_h  [NLAYERS*SSMW*Eh], g_wx_l  [NLAYERS*SSMW*Eh];
__device__ __nv_bfloat16 g_wdt_h [NLAYERS*Eh*64],   g_wdt_l [NLAYERS*Eh*64];
__device__ __nv_bfloat16 g_wout_h[NLAYERS*Dh*Eh],   g_wout_l[NLAYERS*Dh*Eh];

// ---------------- helpers ----------------
__device__ __forceinline__ uint32_t smem_u32(const void* p) {
    uint32_t a;
    asm("{ .reg .u64 t; cvta.to.shared.u64 t, %1; cvt.u32.u64 %0, t; }" : "=r"(a) : "l"(p));
    return a;
}
__device__ __forceinline__ uint32_t pack_bf16x2(float lo, float hi) {
    uint32_t r;
    asm("cvt.rn.satfinite.bf16x2.f32 %0, %1, %2;" : "=r"(r) : "f"(hi), "f"(lo));
    return r;
}
__device__ __forceinline__ void cp16(uint32_t dst, const void* src, bool v) {
    int sz = v ? 16 : 0;
    asm volatile("cp.async.cg.shared.global [%0], [%1], 16, %2;"
                 :: "r"(dst), "l"(src), "r"(sz) : "memory");
}
#define CP_COMMIT() asm volatile("cp.async.commit_group;" ::: "memory")
#define CP_WAIT2()  asm volatile("cp.async.wait_group 2;" ::: "memory")

#define LDSM4(R, addr) \
    asm volatile("ldmatrix.sync.aligned.m8n8.x4.shared.b16 {%0,%1,%2,%3}, [%4];" \
                 : "=r"((R)[0]), "=r"((R)[1]), "=r"((R)[2]), "=r"((R)[3]) : "r"(addr))
#define LDSM2(R, addr) \
    asm volatile("ldmatrix.sync.aligned.m8n8.x2.shared.b16 {%0,%1}, [%2];" \
                 : "=r"((R)[0]), "=r"((R)[1]) : "r"(addr))

#define MMA_BF16(Cacc, Afrag, b0, b1) \
    asm volatile("mma.sync.aligned.m16n8k16.row.col.f32.bf16.bf16.f32 " \
                 "{%0,%1,%2,%3},{%4,%5,%6,%7},{%8,%9},{%0,%1,%2,%3};" \
                 : "+f"((Cacc)[0]), "+f"((Cacc)[1]), "+f"((Cacc)[2]), "+f"((Cacc)[3]) \
                 : "r"((Afrag)[0]), "r"((Afrag)[1]), "r"((Afrag)[2]), "r"((Afrag)[3]), \
                   "r"(b0), "r"(b1))

// ================= split-bf16 GEMM, 3-stage cp.async pipeline =================
// C[m,n] = sum_k A[m,k]*B[n,k]; A split (hi/lo bf16, ld=lda); B split (ld=ldb)
// mode 0: store fp32; mode 1: += extra[m*ldc+n]; mode 2: softplus(acc+extra[n]);
// mode 4: split-K partial store to C + blockIdx.x*ROWS*80 (ld 80, n<80)
#define BKt 32
#define ATILEB 8192                 // 128 rows x 64B

template<int BN>
__global__ void __launch_bounds__(256) gemm_mma2(
    const __nv_bfloat16* __restrict__ Ah_, const __nv_bfloat16* __restrict__ Al_, int lda,
    const __nv_bfloat16* __restrict__ Bh_, const __nv_bfloat16* __restrict__ Bl_, int ldb,
    const float* __restrict__ extra,
    float* __restrict__ C,
    int N, int ldc, int mode, int kCnt)
{
    constexpr int WNT = BN / 4;
    constexpr int NT  = WNT / 8;
    constexpr int BTILEB = BN * 64;
    constexpr int STB = 2 * ATILEB + 2 * BTILEB;
    constexpr int BIT = (BN * 4) / 256;

    extern __shared__ __align__(16) char smraw[];
    uint32_t sb = smem_u32(smraw);

    int tid = threadIdx.x, lane = tid & 31, w = tid >> 5;
    int wm = (w >> 2) * 64, wn = (w & 3) * WNT;
    int bm = blockIdx.y * 128;
    int bn, kStart;
    float* Cp = C;
    if (mode == 4) {
        bn = 0;
        kStart = blockIdx.x * kCnt;
        Cp = C + (size_t)blockIdx.x * ROWS * SSMW;
    } else {
        bn = blockIdx.x * BN;
        kStart = 0;
    }

    float acc[4][NT][4];
    #pragma unroll
    for (int a = 0; a < 4; a++)
        #pragma unroll
        for (int b = 0; b < NT; b++)
            #pragma unroll
            for (int c = 0; c < 4; c++) acc[a][b][c] = 0.f;

    auto prefetch = [&](int c) {
        uint32_t stb = sb + (uint32_t)(c % 3) * STB;
        int k0 = (kStart + c) * BKt;
        #pragma unroll
        for (int i = 0; i < 2; ++i) {
            int idx = tid * 2 + i;
            int r = idx >> 2, c4 = idx & 3;
            uint32_t sw = (uint32_t)(r * 64 + ((c4 ^ ((r >> 1) & 3)) << 4));
            cp16(stb + sw, Ah_ + (size_t)(bm + r) * lda + k0 + c4 * 8, true);
            cp16(stb + ATILEB + sw, Al_ + (size_t)(bm + r) * lda + k0 + c4 * 8, true);
        }
        #pragma unroll
        for (int i = 0; i < BIT; ++i) {
            int idx = tid * BIT + i;
            int r = idx >> 2, c4 = idx & 3;
            uint32_t sw = (uint32_t)(r * 64 + ((c4 ^ ((r >> 1) & 3)) << 4));
            bool bv = (bn + r) < N;
            size_t brow = bv ? (size_t)(bn + r) : 0;
            cp16(stb + 2 * ATILEB + sw, Bh_ + brow * ldb + k0 + c4 * 8, bv);
            cp16(stb + 2 * ATILEB + BTILEB + sw, Bl_ + brow * ldb + k0 + c4 * 8, bv);
        }
        CP_COMMIT();
    };

    #pragma unroll
    for (int i = 0; i < 3; ++i) {
        if (i < kCnt) prefetch(i); else CP_COMMIT();
    }

    for (int c = 0; c < kCnt; ++c) {
        CP_WAIT2();
        __syncthreads();
        uint32_t stb = sb + (uint32_t)(c % 3) * STB;
        int arow = wm + (lane & 15);
        int acol = (lane >> 4) << 3;
        int brow = wn + (lane & 7);
        int bcol = ((lane >> 3) & 1) << 3;

        #pragma unroll
        for (int ks = 0; ks < 2; ++ks) {
            int kk = ks * 16;
            uint32_t ahf[4][4], alf[4][4], bhf[NT][2], blf[NT][2];
            #pragma unroll
            for (int mt = 0; mt < 4; ++mt) {
                int row = arow + mt * 16;
                int j = (acol + kk) >> 3;
                uint32_t ad = stb + (uint32_t)(row * 64 + ((j ^ ((row >> 1) & 3)) << 4));
                LDSM4(ahf[mt], ad);
                LDSM4(alf[mt], ad + ATILEB);
            }
            #pragma unroll
            for (int nt = 0; nt < NT; ++nt) {
                int row = brow + nt * 8;
                int j = (bcol + kk) >> 3;
                uint32_t bd = stb + 2 * ATILEB
                            + (uint32_t)(row * 64 + ((j ^ ((row >> 1) & 3)) << 4));
                LDSM2(bhf[nt], bd);
                LDSM2(blf[nt], bd + BTILEB);
            }
            #pragma unroll
            for (int mt = 0; mt < 4; ++mt)
                #pragma unroll
                for (int nt = 0; nt < NT; ++nt) {
                    MMA_BF16(acc[mt][nt], ahf[mt], bhf[nt][0], bhf[nt][1]);
                    MMA_BF16(acc[mt][nt], ahf[mt], blf[nt][0], blf[nt][1]);
                    MMA_BF16(acc[mt][nt], alf[mt], bhf[nt][0], bhf[nt][1]);
                }
        }
        __syncthreads();
        if (c + 3 < kCnt) prefetch(c + 3); else CP_COMMIT();
    }

    // ---------------- epilogue ----------------
    #pragma unroll
    for (int mt = 0; mt < 4; ++mt) {
        #pragma unroll
        for (int half = 0; half < 2; ++half) {
            int m = bm + wm + mt * 16 + (lane >> 2) + half * 8;
            #pragma unroll
            for (int nt = 0; nt < NT; ++nt) {
                int n = bn + wn + nt * 8 + (lane & 3) * 2;
                float v0 = acc[mt][nt][half * 2 + 0];
                float v1 = acc[mt][nt][half * 2 + 1];
                if (mode == 4) {
                    if (n < SSMW)
                        *(float2*)(Cp + (size_t)m * SSMW + n) = make_float2(v0, v1);
                } else {
                    if (mode == 1) {
                        const float* e = extra + (size_t)m * ldc + n;
                        v0 += e[0]; v1 += e[1];
                    } else if (mode == 2) {
                        v0 += extra[n]; v1 += extra[n + 1];
                        v0 = (v0 > 20.f) ? v0 : log1pf(expf(v0));
                        v1 = (v1 > 20.f) ? v1 : log1pf(expf(v1));
                    }
                    if (n < N)
                        *(float2*)(C + (size_t)m * ldc + n) = make_float2(v0, v1);
                }
            }
        }
    }
}

// ---------------- split-K reduce for x_proj ----------------
__global__ void xreduce_kernel(const float* __restrict__ part,
                               float* __restrict__ ssm,
                               __nv_bfloat16* __restrict__ sh,
                               __nv_bfloat16* __restrict__ sl)
{
    int idx = blockIdx.x * 256 + threadIdx.x;
    if (idx >= ROWS * SSMW) return;
    int r = idx / SSMW, c = idx - r * SSMW;
    float s = part[idx] + part[ROWS * SSMW + idx]
            + part[2 * ROWS * SSMW + idx] + part[3 * ROWS * SSMW + idx];
    ssm[idx] = s;
    if (c < 48) {
        __nv_bfloat16 h = __float2bfloat16(s);
        sh[(size_t)r * 64 + c] = h;
        sl[(size_t)r * 64 + c] = __float2bfloat16(s - __bfloat162float(h));
    } else if (c < 64) {
        sh[(size_t)r * 64 + c] = __float2bfloat16(0.f);
        sl[(size_t)r * 64 + c] = __float2bfloat16(0.f);
    }
}

// ---------------- weight / activation split ----------------
__global__ void split_kernel(const float* __restrict__ src,
                             __nv_bfloat16* __restrict__ dh,
                             __nv_bfloat16* __restrict__ dl,
                             int rows, int cs, int cd)
{
    int idx = blockIdx.x * 256 + threadIdx.x;
    if (idx >= rows * cd) return;
    int r = idx / cd, c = idx - r * cd;
    float v = (c < cs) ? src[(size_t)r * cs + c] : 0.f;
    __nv_bfloat16 h = __float2bfloat16(v);
    dh[idx] = h;
    dl[idx] = __float2bfloat16(v - __bfloat162float(h));
}

// ---------------- small kernels ----------------
__global__ void copy_kernel(const float* __restrict__ src, float* __restrict__ dst, int n) {
    int i = blockIdx.x * 256 + threadIdx.x;
    if (i < n) dst[i] = src[i];
}

__global__ void __launch_bounds__(256) rmsnorm_kernel(
    const float* __restrict__ x, const float* __restrict__ w,
    float* __restrict__ outf,
    __nv_bfloat16* __restrict__ oh, __nv_bfloat16* __restrict__ ol)
{
    __shared__ float sh[8];
    int row = blockIdx.x;
    const float* xr = x + (size_t)row * Dh;
    float s = 0.f;
    #pragma unroll
    for (int i = threadIdx.x; i < Dh; i += 256) { float v = xr[i]; s += v * v; }
    #pragma unroll
    for (int o = 16; o; o >>= 1) s += __shfl_xor_sync(0xffffffffu, s, o);
    int wid = threadIdx.x >> 5, lane = threadIdx.x & 31;
    if (lane == 0) sh[wid] = s;
    __syncthreads();
    if (wid == 0) {
        float v = (lane < 8) ? sh[lane] : 0.f;
        #pragma unroll
        for (int o = 4; o; o >>= 1) v += __shfl_xor_sync(0xffffffffu, v, o);
        if (lane == 0) sh[0] = rsqrtf(v * (1.f / Dh) + EPSV);
    }
    __syncthreads();
    float rs = sh[0];
    #pragma unroll
    for (int i = threadIdx.x; i < Dh; i += 256) {
        float v = xr[i] * rs * w[i];
        size_t o = (size_t)row * Dh + i;
        if (outf) outf[o] = v;
        else {
            __nv_bfloat16 h = __float2bfloat16(v);
            oh[o] = h;
            ol[o] = __float2bfloat16(v - __bfloat162float(h));
        }
    }
}

__global__ void conv_silu_kernel(
    const float* __restrict__ proj,
    const float* __restrict__ cw,
    const float* __restrict__ cb,
    float* __restrict__ out,
    __nv_bfloat16* __restrict__ oh, __nv_bfloat16* __restrict__ ol)
{
    int idx = blockIdx.x * 256 + threadIdx.x;
    if (idx >= ROWS * Eh) return;
    int e  = idx % Eh;
    int bl = idx / Eh;
    int l  = bl % Ll;
    float acc = cb[e];
    #pragma unroll
    for (int k = 0; k < KC; ++k) {
        int ls = l - (KC - 1) + k;
        if (ls >= 0)
            acc += cw[e * KC + k] * proj[(size_t)(bl + ls - l) * (2 * Eh) + e];
    }
    float v = acc / (1.f + __expf(-acc));
    size_t o = (size_t)bl * Eh + e;
    out[o] = v;
    __nv_bfloat16 h = __float2bfloat16(v);
    oh[o] = h;
    ol[o] = __float2bfloat16(v - __bfloat162float(h));
}

// ---------------- selective scan: smem-staged, interleaved shfl ----------------
__global__ void __launch_bounds__(128) scan_kernel(
    const float* __restrict__ dtb,
    const float* __restrict__ ub,
    const float* __restrict__ ssm,
    const float* __restrict__ proj,
    const float* __restrict__ A_log,
    const float* __restrict__ Dskip,
    __nv_bfloat16* __restrict__ yh, __nv_bfloat16* __restrict__ yl)
{
    __shared__ float sdt[64][8], su[64][8], sg[64][8], sB[64][16], sC[64][16];
    int tid = threadIdx.x;
    int blk = blockIdx.x;
    int b   = blk / (Eh / 8);
    int e0  = (blk % (Eh / 8)) * 8;
    int seg = tid >> 4, n = tid & 15;
    int e = e0 + seg;

    float An = -expf(A_log[e * Nst + n]);
    float Dp = Dskip[e];
    float s  = 0.f;
    size_t rowbase = (size_t)b * Ll;

    int t  = tid >> 1, hf = tid & 1;
    int tq = tid >> 2, q  = tid & 3;

    for (int c0 = 0; c0 < Ll; c0 += 64) {
        {
            size_t row = rowbase + c0 + t;
            float4 v;
            v = *(const float4*)(dtb + row * Eh + e0 + hf * 4);
            *(float4*)&sdt[t][hf * 4] = v;
            v = *(const float4*)(ub + row * Eh + e0 + hf * 4);
            *(float4*)&su[t][hf * 4] = v;
            v = *(const float4*)(proj + row * (size_t)(2 * Eh) + Eh + e0 + hf * 4);
            *(float4*)&sg[t][hf * 4] = v;
            #pragma unroll
            for (int hh = 0; hh < 2; ++hh) {
                int tt = tq + hh * 32;
                size_t r2 = rowbase + c0 + tt;
                float4 vb = *(const float4*)(ssm + r2 * SSMW + DTRW + q * 4);
                *(float4*)&sB[tt][q * 4] = vb;
                float4 vc = *(const float4*)(ssm + r2 * SSMW + DTRW + Nst + q * 4);
                *(float4*)&sC[tt][q * 4] = vc;
            }
        }
        __syncthreads();

        for (int tt = 0; tt < 64; tt += 2) {
            float dt0 = sdt[tt][seg],   u0 = su[tt][seg];
            float s0 = s * __expf(dt0 * An) + dt0 * sB[tt][n] * u0;
            float y0 = s0 * sC[tt][n];
            float dt1 = sdt[tt + 1][seg], u1 = su[tt + 1][seg];
            float s1 = s0 * __expf(dt1 * An) + dt1 * sB[tt + 1][n] * u1;
            float y1 = s1 * sC[tt + 1][n];
            s = s1;
            y0 += __shfl_xor_sync(0xffffffffu, y0, 1, 16);
            y1 += __shfl_xor_sync(0xffffffffu, y1, 1, 16);
            y0 += __shfl_xor_sync(0xffffffffu, y0, 2, 16);
            y1 += __shfl_xor_sync(0xffffffffu, y1, 2, 16);
            y0 += __shfl_xor_sync(0xffffffffu, y0, 4, 16);
            y1 += __shfl_xor_sync(0xffffffffu, y1, 4, 16);
            y0 += __shfl_xor_sync(0xffffffffu, y0, 8, 16);
            y1 += __shfl_xor_sync(0xffffffffu, y1, 8, 16);
            if (n == 0) {
                size_t row = rowbase + c0 + tt;
                float g0 = sg[tt][seg];
                float o0 = (y0 + u0 * Dp) * (g0 / (1.f + __expf(-g0)));
                float g1 = sg[tt + 1][seg];
                float o1 = (y1 + u1 * Dp) * (g1 / (1.f + __expf(-g1)));
                __nv_bfloat16 h0 = __float2bfloat16(o0);
                yh[row * Eh + e] = h0;
                yl[row * Eh + e] = __float2bfloat16(o0 - __bfloat162float(h0));
                __nv_bfloat16 h1 = __float2bfloat16(o1);
                yh[(row + 1) * Eh + e] = h1;
                yl[(row + 1) * Eh + e] = __float2bfloat16(o1 - __bfloat162float(h1));
            }
        }
        __syncthreads();
    }
}

// ---------------- driver ----------------
#define SMEM128 (3 * (2*ATILEB + 2*128*64))   // 98304
#define SMEM64  (3 * (2*ATILEB + 2*64*64))    // 73728

extern "C" void kernel_launch(void* const* d_in, const int* in_sizes, int n_in,
                              void* d_out, int out_size)
{
    const float* x       = (const float*)d_in[0];
    const float* norm_w  = (const float*)d_in[1];
    const float* in_w    = (const float*)d_in[2];
    const float* conv_w  = (const float*)d_in[3];
    const float* conv_b  = (const float*)d_in[4];
    const float* xproj_w = (const float*)d_in[5];
    const float* dt_w    = (const float*)d_in[6];
    const float* dt_b    = (const float*)d_in[7];
    const float* A_log   = (const float*)d_in[8];
    const float* D_skip  = (const float*)d_in[9];
    const float* out_w   = (const float*)d_in[10];
    const float* final_w = (const float*)d_in[11];

    float *h, *proj, *u, *ssm, *dt, *xpart;
    __nv_bfloat16 *hn_h, *hn_l, *u_h, *u_l, *ssm_h, *ssm_l, *y_h, *y_l;
    __nv_bfloat16 *win_h, *win_l, *wx_h, *wx_l, *wdt_h, *wdt_l, *wout_h, *wout_l;
    cudaGetSymbolAddress((void**)&h,    g_h);
    cudaGetSymbolAddress((void**)&proj, g_proj);
    cudaGetSymbolAddress((void**)&u,    g_u);
    cudaGetSymbolAddress((void**)&ssm,  g_ssm);
    cudaGetSymbolAddress((void**)&dt,   g_dt);
    cudaGetSymbolAddress((void**)&xpart,g_xpart);
    cudaGetSymbolAddress((void**)&hn_h, g_hn_h);  cudaGetSymbolAddress((void**)&hn_l, g_hn_l);
    cudaGetSymbolAddress((void**)&u_h,  g_u_h);   cudaGetSymbolAddress((void**)&u_l,  g_u_l);
    cudaGetSymbolAddress((void**)&ssm_h,g_ssm_h); cudaGetSymbolAddress((void**)&ssm_l,g_ssm_l);
    cudaGetSymbolAddress((void**)&y_h,  g_y_h);   cudaGetSymbolAddress((void**)&y_l,  g_y_l);
    cudaGetSymbolAddress((void**)&win_h, g_win_h);  cudaGetSymbolAddress((void**)&win_l, g_win_l);
    cudaGetSymbolAddress((void**)&wx_h,  g_wx_h);   cudaGetSymbolAddress((void**)&wx_l,  g_wx_l);
    cudaGetSymbolAddress((void**)&wdt_h, g_wdt_h);  cudaGetSymbolAddress((void**)&wdt_l, g_wdt_l);
    cudaGetSymbolAddress((void**)&wout_h,g_wout_h); cudaGetSymbolAddress((void**)&wout_l,g_wout_l);

    cudaFuncSetAttribute(gemm_mma2<128>, cudaFuncAttributeMaxDynamicSharedMemorySize, SMEM128);
    cudaFuncSetAttribute(gemm_mma2<64>,  cudaFuncAttributeMaxDynamicSharedMemorySize, SMEM64);

    // split all weights
    {
        int n1 = NLAYERS * 2 * Eh * Dh;
        split_kernel<<<(n1 + 255) / 256, 256>>>(in_w, win_h, win_l, NLAYERS * 2 * Eh, Dh, Dh);
        int n2 = NLAYERS * SSMW * Eh;
        split_kernel<<<(n2 + 255) / 256, 256>>>(xproj_w, wx_h, wx_l, NLAYERS * SSMW, Eh, Eh);
        int n3 = NLAYERS * Eh * 64;
        split_kernel<<<(n3 + 255) / 256, 256>>>(dt_w, wdt_h, wdt_l, NLAYERS * Eh, DTRW, 64);
        int n4 = NLAYERS * Dh * Eh;
        split_kernel<<<(n4 + 255) / 256, 256>>>(out_w, wout_h, wout_l, NLAYERS * Dh, Eh, Eh);
    }

    copy_kernel<<<(ROWS * Dh + 255) / 256, 256>>>(x, h, ROWS * Dh);

    for (int l = 0; l < NLAYERS; ++l) {
        rmsnorm_kernel<<<ROWS, 256>>>(h, norm_w + (size_t)l * Dh, nullptr, hn_h, hn_l);

        // in_proj -> proj (fp32); BN=128
        {
            dim3 grid(2 * Eh / 128, ROWS / 128);
            gemm_mma2<128><<<grid, 256, SMEM128>>>(hn_h, hn_l, Dh,
                win_h + (size_t)l * 2 * Eh * Dh, win_l + (size_t)l * 2 * Eh * Dh, Dh,
                nullptr, proj, 2 * Eh, 2 * Eh, 0, Dh / BKt);
        }

        conv_silu_kernel<<<(ROWS * Eh + 255) / 256, 256>>>(
            proj, conv_w + (size_t)l * Eh * KC, conv_b + (size_t)l * Eh, u, u_h, u_l);

        // x_proj split-K4 -> partials; BN=128, mode 4
        {
            dim3 grid(4, ROWS / 128);
            gemm_mma2<128><<<grid, 256, SMEM128>>>(u_h, u_l, Eh,
                wx_h + (size_t)l * SSMW * Eh, wx_l + (size_t)l * SSMW * Eh, Eh,
                nullptr, xpart, SSMW, SSMW, 4, (Eh / BKt) / 4);
        }
        xreduce_kernel<<<(ROWS * SSMW + 255) / 256, 256>>>(xpart, ssm, ssm_h, ssm_l);

        // dt_proj + softplus -> dt fp32; BN=128
        {
            dim3 grid(Eh / 128, ROWS / 128);
            gemm_mma2<128><<<grid, 256, SMEM128>>>(ssm_h, ssm_l, 64,
                wdt_h + (size_t)l * Eh * 64, wdt_l + (size_t)l * Eh * 64, 64,
                dt_b + (size_t)l * Eh, dt, Eh, Eh, 2, 64 / BKt);
        }

        scan_kernel<<<Bb * Eh / 8, 128>>>(
            dt, u, ssm, proj,
            A_log + (size_t)l * Eh * Nst, D_skip + (size_t)l * Eh, y_h, y_l);

        // out_proj + residual -> h; BN=64
        {
            dim3 grid(Dh / 64, ROWS / 128);
            gemm_mma2<64><<<grid, 256, SMEM64>>>(y_h, y_l, Eh,
                wout_h + (size_t)l * Dh * Eh, wout_l + (size_t)l * Dh * Eh, Eh,
                h, h, Dh, Dh, 1, Eh / BKt);
        }
    }

    rmsnorm_kernel<<<ROWS, 256>>>(h, final_w, (float*)d_out, nullptr, nullptr);
}